// round 2
// baseline (speedup 1.0000x reference)
#include <cuda_runtime.h>
#include <math.h>

#define VOCAB   30522
#define NROWS   4096
#define HALFV   15261   /* VOCAB/2 exact */
#define DIM     768
#define P_LINE  224
#define N_LINE  224
#define P_QUAT  64
#define N_QUAT  64
#define B_SON   16
#define TEMP_INV (1.0f/0.07f)

#define W_MLM    0.5f
#define W_LINE   0.2f
#define W_QUAT   0.2f
#define W_SONNET 0.1f

// ---- scratch (__device__ globals: no allocations allowed) ----
// normalized rows layout:
//   [0,224)   line_anchor   [224,448) line_positive  [448,672) line_negative
//   [672,736) quat_anchor   [736,800) quat_positive  [800,864) quat_negative
//   [864,880) sonnet
__device__ float g_norm[880 * DIM];
__device__ int   g_label[NROWS];
__device__ float g_nll[NROWS];
__device__ float g_loss_line[P_LINE];
__device__ float g_loss_quat[P_QUAT];
__device__ float g_loss_son[B_SON];

__device__ __forceinline__ float warp_sum(float v) {
#pragma unroll
    for (int o = 16; o; o >>= 1) v += __shfl_xor_sync(0xffffffffu, v, o);
    return v;
}
__device__ __forceinline__ float warp_max(float v) {
#pragma unroll
    for (int o = 16; o; o >>= 1) v = fmaxf(v, __shfl_xor_sync(0xffffffffu, v, o));
    return v;
}

// ============================================================================
// K0: normalize all small tensors into g_norm (blocks 0..879) and decode
//     labels into g_label (blocks 880..895). Handles both int32 and int64
//     label storage via a layout sniff (odd 32-bit words all in {0,-1} => i64).
// ============================================================================
__global__ void __launch_bounds__(256) k_prep(
    const float* __restrict__ la, const float* __restrict__ lp,
    const float* __restrict__ ln, const float* __restrict__ qa,
    const float* __restrict__ qp, const float* __restrict__ qn,
    const float* __restrict__ se, const int* __restrict__ labels32)
{
    int b = blockIdx.x;
    if (b < 880) {
        const float* src; int row;
        if      (b < 224) { src = la; row = b;       }
        else if (b < 448) { src = lp; row = b - 224; }
        else if (b < 672) { src = ln; row = b - 448; }
        else if (b < 736) { src = qa; row = b - 672; }
        else if (b < 800) { src = qp; row = b - 736; }
        else if (b < 864) { src = qn; row = b - 800; }
        else              { src = se; row = b - 864; }
        const float* x = src + (size_t)row * DIM;

        float ss = 0.f;
        for (int d = threadIdx.x; d < DIM; d += 256) { float v = x[d]; ss += v * v; }
        __shared__ float red[8];
        __shared__ float s_inv;
        ss = warp_sum(ss);
        if ((threadIdx.x & 31) == 0) red[threadIdx.x >> 5] = ss;
        __syncthreads();
        if (threadIdx.x < 32) {
            float v = (threadIdx.x < 8) ? red[threadIdx.x] : 0.f;
            v = warp_sum(v);
            if (threadIdx.x == 0) s_inv = 1.0f / fmaxf(sqrtf(v), 1e-12f);
        }
        __syncthreads();
        float inv = s_inv;
        for (int d = threadIdx.x; d < DIM; d += 256)
            g_norm[(size_t)b * DIM + d] = x[d] * inv;
    } else {
        // ---- label decode ----
        __shared__ int s_is64;
        if (threadIdx.x == 0) {
            int ok = 1;
            for (int k = 1; k < 128; k += 2) {
                int w = labels32[k];
                if (w != 0 && w != -1) { ok = 0; break; }
            }
            s_is64 = ok;
        }
        __syncthreads();
        int i = (b - 880) * 256 + threadIdx.x;       // 0..4095
        int lab = s_is64 ? labels32[2 * i] : labels32[i];
        g_label[i] = lab;
    }
}

// ============================================================================
// K1: MLM per-row NLL. One block per row; rows with label<0 exit immediately
//     (only ~15% of the 500MB tensor is ever read). Single pass, no max
//     subtraction (logits ~N(0,1): sum(exp) ~5e4, safe in fp32).
//     unroll 8 -> 64B of loads in flight per thread to cover DRAM latency.
// ============================================================================
__global__ void __launch_bounds__(256) k_mlm(const float* __restrict__ logits)
{
    int r = blockIdx.x;
    int label = g_label[r];
    if (label < 0) {
        if (threadIdx.x == 0) g_nll[r] = 0.f;
        return;
    }
    const float2* row = reinterpret_cast<const float2*>(logits + (size_t)r * VOCAB);
    float s0 = 0.f, s1 = 0.f;
#pragma unroll 8
    for (int i = threadIdx.x; i < HALFV; i += 256) {
        float2 v = __ldg(row + i);
        s0 += __expf(v.x);
        s1 += __expf(v.y);
    }
    float s = s0 + s1;
    __shared__ float red[8];
    s = warp_sum(s);
    if ((threadIdx.x & 31) == 0) red[threadIdx.x >> 5] = s;
    __syncthreads();
    if (threadIdx.x == 0) {
        float t = 0.f;
#pragma unroll
        for (int w = 0; w < 8; w++) t += red[w];
        float xl = __ldg(logits + (size_t)r * VOCAB + label);
        g_nll[r] = __logf(t) - xl;
    }
}

// ============================================================================
// K2: fused line/quat/sonnet InfoNCE. 8 anchors per block (cached in smem),
//     warp-per-negative coalesced dot products, then per-anchor logsumexp.
//     Sonnet runs in "self" mode (diag is the positive, included in the lse).
//     Grid: 28 (line) + 8 (quat) + 2 (sonnet) = 38 blocks.
// ============================================================================
__global__ void __launch_bounds__(256) k_small()
{
    int b = blockIdx.x;
    const float *A, *Pv, *Ng;
    float* out;
    int N, a0, self;
    if (b < 28) {
        A = g_norm;                 Pv = g_norm + 224 * DIM; Ng = g_norm + 448 * DIM;
        out = g_loss_line; N = N_LINE; a0 = b * 8; self = 0;
    } else if (b < 36) {
        A = g_norm + 672 * DIM;     Pv = g_norm + 736 * DIM; Ng = g_norm + 800 * DIM;
        out = g_loss_quat; N = N_QUAT; a0 = (b - 28) * 8; self = 0;
    } else {
        A = g_norm + 864 * DIM;     Pv = A;                  Ng = A;
        out = g_loss_son;  N = B_SON;  a0 = (b - 36) * 8; self = 1;
    }

    __shared__ float a_sm[8][DIM];
    __shared__ float sims[8][N_LINE];

    for (int t = threadIdx.x; t < 8 * DIM; t += 256) {
        int i = t / DIM, d = t % DIM;
        a_sm[i][d] = A[(size_t)(a0 + i) * DIM + d];
    }
    __syncthreads();

    int warp = threadIdx.x >> 5, lane = threadIdx.x & 31;

    for (int j = warp; j < N; j += 8) {
        float acc[8];
#pragma unroll
        for (int i = 0; i < 8; i++) acc[i] = 0.f;
        const float* nrow = Ng + (size_t)j * DIM;
#pragma unroll 4
        for (int k = 0; k < DIM / 32; k++) {
            int d = lane + 32 * k;
            float nv = nrow[d];
#pragma unroll
            for (int i = 0; i < 8; i++) acc[i] += nv * a_sm[i][d];
        }
#pragma unroll
        for (int i = 0; i < 8; i++) acc[i] = warp_sum(acc[i]);
        if (lane == 0) {
#pragma unroll
            for (int i = 0; i < 8; i++) sims[i][j] = acc[i] * TEMP_INV;
        }
    }
    __syncthreads();

    // one warp per anchor
    {
        int i = warp;
        int gi = a0 + i;
        float pos;
        if (self) {
            pos = sims[i][gi];
        } else {
            float d0 = 0.f;
            const float* prow = Pv + (size_t)gi * DIM;
#pragma unroll 4
            for (int k = 0; k < DIM / 32; k++) {
                int d = lane + 32 * k;
                d0 += prow[d] * a_sm[i][d];
            }
            d0 = warp_sum(d0);
            pos = __shfl_sync(0xffffffffu, d0, 0) * TEMP_INV;
        }
        float m = self ? -1e30f : pos;
        for (int j = lane; j < N; j += 32) m = fmaxf(m, sims[i][j]);
        m = warp_max(m);
        float se = 0.f;
        for (int j = lane; j < N; j += 32) se += __expf(sims[i][j] - m);
        se = warp_sum(se);
        if (lane == 0) {
            if (!self) se += __expf(pos - m);
            out[gi] = m + __logf(se) - pos;
        }
    }
}

// ============================================================================
// K3: deterministic final reduction + weighted combine -> d_out[0]
// ============================================================================
__global__ void __launch_bounds__(1024) k_final(float* __restrict__ out)
{
    int t = threadIdx.x, lane = t & 31, warp = t >> 5;
    float nll = 0.f, line = 0.f, quat = 0.f, son = 0.f;
    float cnt = 0.f;
    for (int i = t; i < NROWS; i += 1024) {
        nll += g_nll[i];
        cnt += (g_label[i] >= 0) ? 1.f : 0.f;
    }
    for (int i = t; i < P_LINE; i += 1024) line += g_loss_line[i];
    for (int i = t; i < P_QUAT; i += 1024) quat += g_loss_quat[i];
    for (int i = t; i < B_SON;  i += 1024) son  += g_loss_son[i];

    __shared__ float r0[32], r1[32], r2[32], r3[32], r4[32];
    nll  = warp_sum(nll);
    cnt  = warp_sum(cnt);
    line = warp_sum(line);
    quat = warp_sum(quat);
    son  = warp_sum(son);
    if (lane == 0) { r0[warp]=nll; r1[warp]=cnt; r2[warp]=line; r3[warp]=quat; r4[warp]=son; }
    __syncthreads();
    if (t < 32) {
        float a = r0[t], b = r1[t], c = r2[t], d = r3[t], e = r4[t];
        a = warp_sum(a); b = warp_sum(b); c = warp_sum(c); d = warp_sum(d); e = warp_sum(e);
        if (t == 0) {
            float mlm  = a / fmaxf(b, 1.f);
            float lln  = c * (1.0f / (float)P_LINE);
            float lqt  = d * (1.0f / (float)P_QUAT);
            float lsn  = e * (1.0f / (float)B_SON);
            out[0] = W_MLM * mlm + W_LINE * lln + W_QUAT * lqt + W_SONNET * lsn;
        }
    }
}

// ============================================================================
extern "C" void kernel_launch(void* const* d_in, const int* in_sizes, int n_in,
                              void* d_out, int out_size)
{
    const float* logits = (const float*)d_in[0];
    const int*   labels = (const int*)  d_in[1];
    const float* la = (const float*)d_in[2];
    const float* lp = (const float*)d_in[3];
    const float* ln = (const float*)d_in[4];
    const float* qa = (const float*)d_in[5];
    const float* qp = (const float*)d_in[6];
    const float* qn = (const float*)d_in[7];
    const float* se = (const float*)d_in[8];

    k_prep <<<896, 256>>>(la, lp, ln, qa, qp, qn, se, labels);
    k_mlm  <<<NROWS, 256>>>(logits);
    k_small<<<38, 256>>>();
    k_final<<<1, 1024>>>((float*)d_out);
}

// round 3
// speedup vs baseline: 2.1483x; 2.1483x over previous
#include <cuda_runtime.h>
#include <math.h>
#include <stdint.h>

#define VOCAB   30522
#define NROWS   4096
#define DIM     768
#define P_LINE  224
#define N_LINE  224
#define P_QUAT  64
#define N_QUAT  64
#define B_SON   16
#define TEMP_INV (1.0f/0.07f)

#define W_MLM    0.5f
#define W_LINE   0.2f
#define W_QUAT   0.2f
#define W_SONNET 0.1f

// global anchor index space: line [0,224), quat [224,288), sonnet [288,304)
#define NANCH   304
#define MAXCHUNK 8

// ---- scratch (__device__ globals) ----
// g_norm rows: [0,224) line_a  [224,448) line_p  [448,672) line_n
//              [672,736) quat_a [736,800) quat_p [800,864) quat_n  [864,880) sonnet
__device__ float g_norm[880 * DIM];
__device__ int   g_label[NROWS];
__device__ int   g_list[NROWS];
__device__ int   g_nvalid;
__device__ float g_nll[NROWS];
__device__ float g_pos[NANCH];
__device__ float g_part[NANCH * MAXCHUNK];

__device__ __forceinline__ float warp_sum(float v) {
#pragma unroll
    for (int o = 16; o; o >>= 1) v += __shfl_xor_sync(0xffffffffu, v, o);
    return v;
}

// ============================================================================
// K0: blocks 0..879 L2-normalize small tensors into g_norm (float4 path).
//     block 880: decode labels (int32/int64 sniff) + deterministic block-level
//     compaction of valid rows into g_list / g_nvalid.
// ============================================================================
__global__ void __launch_bounds__(256) k_prep(
    const float* __restrict__ la, const float* __restrict__ lp,
    const float* __restrict__ ln, const float* __restrict__ qa,
    const float* __restrict__ qp, const float* __restrict__ qn,
    const float* __restrict__ se, const int* __restrict__ labels32)
{
    int b = blockIdx.x;
    int t = threadIdx.x;
    if (b < 880) {
        const float* src; int row;
        if      (b < 224) { src = la; row = b;       }
        else if (b < 448) { src = lp; row = b - 224; }
        else if (b < 672) { src = ln; row = b - 448; }
        else if (b < 736) { src = qa; row = b - 672; }
        else if (b < 800) { src = qp; row = b - 736; }
        else if (b < 864) { src = qn; row = b - 800; }
        else              { src = se; row = b - 864; }
        const float4* x4 = reinterpret_cast<const float4*>(src + (size_t)row * DIM);
        float4* o4 = reinterpret_cast<float4*>(g_norm + (size_t)b * DIM);

        float4 v = make_float4(0.f, 0.f, 0.f, 0.f);
        float ss = 0.f;
        if (t < DIM / 4) {                 // 192 active threads, 1 iter
            v = x4[t];
            ss = v.x * v.x + v.y * v.y + v.z * v.z + v.w * v.w;
        }
        __shared__ float red[8];
        __shared__ float s_inv;
        ss = warp_sum(ss);
        if ((t & 31) == 0) red[t >> 5] = ss;
        __syncthreads();
        if (t < 32) {
            float s = (t < 8) ? red[t] : 0.f;
            s = warp_sum(s);
            if (t == 0) s_inv = 1.0f / fmaxf(sqrtf(s), 1e-12f);
        }
        __syncthreads();
        if (t < DIM / 4) {
            float inv = s_inv;
            o4[t] = make_float4(v.x * inv, v.y * inv, v.z * inv, v.w * inv);
        }
    } else {
        // ---- label decode + compaction (single block, deterministic) ----
        __shared__ int s_is64;
        __shared__ int w_tot[8];
        __shared__ int w_off[8];
        if (t == 0) {
            int ok = 1;
            for (int k = 1; k < 128; k += 2) {
                int w = labels32[k];
                if (w != 0 && w != -1) { ok = 0; break; }
            }
            s_is64 = ok;
        }
        __syncthreads();
        int is64 = s_is64;
        int labs[16];
        int cnt = 0;
        int i0 = t * 16;
#pragma unroll
        for (int k = 0; k < 16; k++) {
            int i = i0 + k;
            int lab = is64 ? labels32[2 * i] : labels32[i];
            g_label[i] = lab;
            labs[k] = lab;
            cnt += (lab >= 0);
        }
        // warp-exclusive scan of cnt
        int lane = t & 31, warp = t >> 5;
        int incl = cnt;
#pragma unroll
        for (int o = 1; o < 32; o <<= 1) {
            int x = __shfl_up_sync(0xffffffffu, incl, o);
            if (lane >= o) incl += x;
        }
        int excl = incl - cnt;
        if (lane == 31) w_tot[warp] = incl;
        __syncthreads();
        if (t == 0) {
            int run = 0;
#pragma unroll
            for (int w = 0; w < 8; w++) { w_off[w] = run; run += w_tot[w]; }
            g_nvalid = run;
        }
        __syncthreads();
        int base = w_off[warp] + excl;
#pragma unroll
        for (int k = 0; k < 16; k++) {
            if (labs[k] >= 0) g_list[base++] = i0 + k;
        }
    }
}

// ============================================================================
// K1: MLM per-row NLL over COMPACTED valid rows only (~15% of 500MB read).
//     Fixed grid of 1184 blocks (8/SM), block b handles g_list[b] (loop for
//     safety). float4 main loop with head-peel for 8-mod-16 row alignment.
//     No max subtraction (logits ~N(0,1): sum(exp) ~5e4, safe in fp32).
// ============================================================================
#define MLM_GRID 1184
__global__ void __launch_bounds__(256) k_mlm(const float* __restrict__ logits)
{
    int nv = g_nvalid;
    for (int idx = blockIdx.x; idx < nv; idx += MLM_GRID) {
        int r = g_list[idx];
        const float* rowp = logits + (size_t)r * VOCAB;
        int mis = ((int)((uintptr_t)rowp & 15)) >> 2;   // misalignment in floats (0 or 2)
        int head = mis ? (4 - mis) : 0;
        int n4 = (VOCAB - head) >> 2;
        int tail = VOCAB - head - n4 * 4;

        const float4* p4 = reinterpret_cast<const float4*>(rowp + head);
        float s0 = 0.f, s1 = 0.f, s2 = 0.f, s3 = 0.f;
#pragma unroll 8
        for (int i = threadIdx.x; i < n4; i += 256) {
            float4 v = __ldg(p4 + i);
            s0 += __expf(v.x);
            s1 += __expf(v.y);
            s2 += __expf(v.z);
            s3 += __expf(v.w);
        }
        float s = (s0 + s1) + (s2 + s3);
        if (threadIdx.x == 0) {
            for (int k = 0; k < head; k++) s += __expf(__ldg(rowp + k));
        } else if (threadIdx.x == 1) {
            for (int k = 0; k < tail; k++) s += __expf(__ldg(rowp + head + n4 * 4 + k));
        }
        __shared__ float red[8];
        s = warp_sum(s);
        if ((threadIdx.x & 31) == 0) red[threadIdx.x >> 5] = s;
        __syncthreads();
        if (threadIdx.x == 0) {
            float tot = 0.f;
#pragma unroll
            for (int w = 0; w < 8; w++) tot += red[w];
            int label = g_label[r];
            float xl = __ldg(rowp + label);
            g_nll[r] = __logf(tot) - xl;
        }
        __syncthreads();   // red[] reuse across loop iterations
    }
}

// ============================================================================
// K2: chunked InfoNCE partial exp-sums. Sims are bounded (|sim/T| <= ~14.3)
//     so no max-subtraction is needed: accumulate exp(sim/T) directly.
//     Block layout (8 anchors x 32-neg chunk each, 256 thr):
//       [0,196)   line : 28 anchor-groups x 7 chunks
//       [196,212) quat : 8 anchor-groups x 2 chunks
//       [212,214) sonnet (self): 2 anchor-groups x 1 chunk of 16
//     chunk==0 blocks also compute the positive sims (warp w -> anchor w).
// ============================================================================
__global__ void __launch_bounds__(256) k_small()
{
    int b = blockIdx.x;
    const float *A, *Pv, *Ng;
    int a0, nbase, nneg, chunk, gidx0, self;
    if (b < 196) {
        int ag = b / 7; chunk = b % 7;
        A = g_norm;                Pv = g_norm + 224 * DIM; Ng = g_norm + 448 * DIM;
        a0 = ag * 8; nbase = chunk * 32; nneg = 32; gidx0 = a0; self = 0;
    } else if (b < 212) {
        int bb = b - 196; int ag = bb / 2; chunk = bb % 2;
        A = g_norm + 672 * DIM;    Pv = g_norm + 736 * DIM; Ng = g_norm + 800 * DIM;
        a0 = ag * 8; nbase = chunk * 32; nneg = 32; gidx0 = 224 + a0; self = 0;
    } else {
        int ag = b - 212; chunk = 0;
        A = g_norm + 864 * DIM;    Pv = A;                  Ng = A;
        a0 = ag * 8; nbase = 0; nneg = 16; gidx0 = 288 + a0; self = 1;
    }

    __shared__ float a_sm[8][DIM];
    __shared__ float part_sm[8][8];     // [warp][anchor]

    int t = threadIdx.x, warp = t >> 5, lane = t & 31;

    // load 8 anchor rows (float4)
    {
        const float4* src = reinterpret_cast<const float4*>(A + (size_t)a0 * DIM);
        float4* dst = reinterpret_cast<float4*>(&a_sm[0][0]);
        for (int i = t; i < 8 * DIM / 4; i += 256) dst[i] = src[i];
    }
    __syncthreads();

    float p[8];
#pragma unroll
    for (int i = 0; i < 8; i++) p[i] = 0.f;

    for (int jj = warp; jj < nneg; jj += 8) {
        int j = nbase + jj;
        const float* nrow = Ng + (size_t)j * DIM;
        float acc[8];
#pragma unroll
        for (int i = 0; i < 8; i++) acc[i] = 0.f;
#pragma unroll 4
        for (int k = 0; k < DIM / 32; k++) {
            int d = lane + 32 * k;
            float nv = __ldg(nrow + d);
#pragma unroll
            for (int i = 0; i < 8; i++) acc[i] += nv * a_sm[i][d];
        }
#pragma unroll
        for (int i = 0; i < 8; i++) acc[i] = warp_sum(acc[i]);
        if (lane < 8) {
            float sim = acc[lane] * TEMP_INV;   // lane i holds anchor i's reduced value? no:
        }
        // lane 0 accumulates all 8 (warp_sum leaves value in every lane)
        if (lane == 0) {
#pragma unroll
            for (int i = 0; i < 8; i++) {
                float sim = acc[i] * TEMP_INV;
                p[i] += __expf(sim);
                if (self && (a0 + i) == j) g_pos[gidx0 + i] = sim;
            }
        }
    }
    if (lane == 0) {
#pragma unroll
        for (int i = 0; i < 8; i++) part_sm[warp][i] = p[i];
    }

    // positives for non-self chunk-0 blocks: warp w -> anchor w
    if (!self && chunk == 0) {
        const float* prow = Pv + (size_t)(a0 + warp) * DIM;
        float d0 = 0.f;
#pragma unroll 4
        for (int k = 0; k < DIM / 32; k++) {
            int d = lane + 32 * k;
            d0 += __ldg(prow + d) * a_sm[warp][d];
        }
        d0 = warp_sum(d0);
        if (lane == 0) g_pos[gidx0 + warp] = d0 * TEMP_INV;
    }
    __syncthreads();

    if (t < 8) {
        float s = 0.f;
#pragma unroll
        for (int w = 0; w < 8; w++) s += part_sm[w][t];
        g_part[(gidx0 + t) * MAXCHUNK + chunk] = s;
    }
}

// ============================================================================
// K3: finish per-anchor losses + deterministic weighted combine -> d_out[0]
// ============================================================================
__global__ void __launch_bounds__(1024) k_final(float* __restrict__ out)
{
    int t = threadIdx.x, lane = t & 31, warp = t >> 5;
    int nv = g_nvalid;

    float contrib = 0.f;
    if (t < 224) {                       // line
        float s = 0.f;
#pragma unroll
        for (int c = 0; c < 7; c++) s += g_part[t * MAXCHUNK + c];
        float pos = g_pos[t];
        contrib = (W_LINE / (float)P_LINE) * (__logf(s + __expf(pos)) - pos);
    } else if (t < 288) {                // quat
        float s = g_part[t * MAXCHUNK + 0] + g_part[t * MAXCHUNK + 1];
        float pos = g_pos[t];
        contrib = (W_QUAT / (float)P_QUAT) * (__logf(s + __expf(pos)) - pos);
    } else if (t < 304) {                // sonnet (diag already inside sum)
        float s = g_part[t * MAXCHUNK + 0];
        float pos = g_pos[t];
        contrib = (W_SONNET / (float)B_SON) * (__logf(s) - pos);
    }

    float nll = 0.f;
    for (int i = t; i < nv; i += 1024) nll += g_nll[g_list[i]];

    __shared__ float r0[32], r1[32];
    contrib = warp_sum(contrib);
    nll     = warp_sum(nll);
    if (lane == 0) { r0[warp] = contrib; r1[warp] = nll; }
    __syncthreads();
    if (t < 32) {
        float a = r0[t], b = r1[t];
        a = warp_sum(a);
        b = warp_sum(b);
        if (t == 0) {
            float mlm = b / fmaxf((float)nv, 1.f);
            out[0] = a + W_MLM * mlm;
        }
    }
}

// ============================================================================
extern "C" void kernel_launch(void* const* d_in, const int* in_sizes, int n_in,
                              void* d_out, int out_size)
{
    const float* logits = (const float*)d_in[0];
    const int*   labels = (const int*)  d_in[1];
    const float* la = (const float*)d_in[2];
    const float* lp = (const float*)d_in[3];
    const float* ln = (const float*)d_in[4];
    const float* qa = (const float*)d_in[5];
    const float* qp = (const float*)d_in[6];
    const float* qn = (const float*)d_in[7];
    const float* se = (const float*)d_in[8];

    k_prep <<<881, 256>>>(la, lp, ln, qa, qp, qn, se, labels);
    k_mlm  <<<MLM_GRID, 256>>>(logits);
    k_small<<<214, 256>>>();
    k_final<<<1, 1024>>>((float*)d_out);
}

// round 6
// speedup vs baseline: 3.1612x; 1.4715x over previous
#include <cuda_runtime.h>
#include <math.h>
#include <stdint.h>

#define VOCAB   30522
#define NROWS   4096
#define DIM     768
#define P_LINE  224
#define N_LINE  224
#define P_QUAT  64
#define N_QUAT  64
#define B_SON   16
#define TEMP_INV (1.0f/0.07f)

#define W_MLM    0.5f
#define W_LINE   0.2f
#define W_QUAT   0.2f
#define W_SONNET 0.1f

// global anchor index space: line [0,224), quat [224,288), sonnet [288,304)
#define NANCH    304
#define MAXCHUNK 8
// small-path blocks: 196 line (28 groups x 7 chunks) + 16 quat (8x2) + 2 sonnet
#define SMALL_BLOCKS 214
#define GRID_MAIN (SMALL_BLOCKS + NROWS)

// ---- scratch (__device__ globals; no allocations allowed) ----
__device__ float g_nll[NROWS];              // valid rows only; gated by label in k_final
__device__ float g_pos[NANCH];
__device__ float g_part[NANCH * MAXCHUNK];

__device__ __forceinline__ float warp_sum(float v) {
#pragma unroll
    for (int o = 16; o; o >>= 1) v += __shfl_xor_sync(0xffffffffu, v, o);
    return v;
}

// int64-vs-int32 label layout sniff: odd 32-bit words of an int64 little-endian
// label array are sign extensions in {0,-1}; int32 labels there would be real
// vocab ids (never -1, 0 with prob ~0). 8 L2-cached loads.
__device__ __forceinline__ int sniff_is64(const int* __restrict__ labels32) {
    int ok = 1;
#pragma unroll
    for (int k = 1; k < 16; k += 2) {
        int w = labels32[k];
        if (w != 0 && w != -1) { ok = 0; }
    }
    return ok;
}

// ============================================================================
// K_MAIN: one fused kernel.
//   blocks [0,214): chunked InfoNCE with normalize-on-the-fly (raw inputs).
//   blocks [214,4310): MLM row r = b-214; inline label decode; dead rows exit
//     immediately with no global writes (~85% of blocks).
// MLM: single pass, no max subtraction (logits ~N(0,1): sum(exp)~5e4, fp32-safe).
// InfoNCE: |sim/T| <= 14.3 -> exp never overflows; accumulate exp directly.
// ============================================================================
__global__ void __launch_bounds__(256) k_main(
    const float* __restrict__ logits, const int* __restrict__ labels32,
    const float* __restrict__ la, const float* __restrict__ lp,
    const float* __restrict__ ln, const float* __restrict__ qa,
    const float* __restrict__ qp, const float* __restrict__ qn,
    const float* __restrict__ se)
{
    __shared__ float s_a[8][DIM];        // normalized anchor cache (small path)
    __shared__ float s_part[8][8];       // [warp][anchor] exp-sum partials
    __shared__ float s_red[8];           // mlm block reduction
    __shared__ int   s_lab;

    const int b = blockIdx.x;
    const int t = threadIdx.x;
    const int warp = t >> 5, lane = t & 31;

    if (b >= SMALL_BLOCKS) {
        // ---------------- MLM path ----------------
        const int r = b - SMALL_BLOCKS;
        if (t == 0) {
            int is64 = sniff_is64(labels32);
            s_lab = is64 ? labels32[2 * r] : labels32[r];
        }
        __syncthreads();
        const int label = s_lab;
        if (label < 0) return;           // dead block: no writes at all

        const float* rowp = logits + (size_t)r * VOCAB;
        const int mis  = ((int)((uintptr_t)rowp & 15)) >> 2;   // floats (0 or 2)
        const int head = mis ? (4 - mis) : 0;
        const int n4   = (VOCAB - head) >> 2;
        const int tail = VOCAB - head - n4 * 4;

        const float4* p4 = reinterpret_cast<const float4*>(rowp + head);
        float s0 = 0.f, s1 = 0.f, s2 = 0.f, s3 = 0.f;
#pragma unroll 8
        for (int i = t; i < n4; i += 256) {
            float4 v = __ldg(p4 + i);
            s0 += __expf(v.x);
            s1 += __expf(v.y);
            s2 += __expf(v.z);
            s3 += __expf(v.w);
        }
        float s = (s0 + s1) + (s2 + s3);
        if (t == 0) {
            for (int k = 0; k < head; k++) s += __expf(__ldg(rowp + k));
        } else if (t == 1) {
            for (int k = 0; k < tail; k++) s += __expf(__ldg(rowp + head + n4 * 4 + k));
        }
        s = warp_sum(s);
        if (lane == 0) s_red[warp] = s;
        __syncthreads();
        if (t == 0) {
            float tot = 0.f;
#pragma unroll
            for (int w = 0; w < 8; w++) tot += s_red[w];
            float xl = __ldg(rowp + label);
            g_nll[r] = __logf(tot) - xl;
        }
        return;
    }

    // ---------------- small InfoNCE path ----------------
    const float *A, *Pv, *Ng;
    int a0, nbase, nneg, chunk, gidx0, self;
    if (b < 196) {
        int ag = b / 7; chunk = b % 7;
        A = la; Pv = lp; Ng = ln;
        a0 = ag * 8; nbase = chunk * 32; nneg = 32; gidx0 = a0; self = 0;
    } else if (b < 212) {
        int bb = b - 196; int ag = bb / 2; chunk = bb % 2;
        A = qa; Pv = qp; Ng = qn;
        a0 = ag * 8; nbase = chunk * 32; nneg = 32; gidx0 = 224 + a0; self = 0;
    } else {
        int ag = b - 212; chunk = 0;
        A = se; Pv = se; Ng = se;
        a0 = ag * 8; nbase = 0; nneg = 16; gidx0 = 288 + a0; self = 1;
    }

    // warp w: load raw anchor row w, normalize, store to smem
    {
        const float* arow = A + (size_t)(a0 + warp) * DIM;
        float av[DIM / 32];
        float ss = 0.f;
#pragma unroll
        for (int k = 0; k < DIM / 32; k++) {
            float v = __ldg(arow + lane + 32 * k);
            av[k] = v;
            ss += v * v;
        }
        ss = warp_sum(ss);
        float inv = 1.0f / fmaxf(sqrtf(ss), 1e-12f);
#pragma unroll
        for (int k = 0; k < DIM / 32; k++) s_a[warp][lane + 32 * k] = av[k] * inv;
    }
    __syncthreads();

    float p[8];
#pragma unroll
    for (int i = 0; i < 8; i++) p[i] = 0.f;

    for (int jj = warp; jj < nneg; jj += 8) {
        int j = nbase + jj;
        const float* nrow = Ng + (size_t)j * DIM;
        float acc[8];
        float nn = 0.f;
#pragma unroll
        for (int i = 0; i < 8; i++) acc[i] = 0.f;
#pragma unroll 4
        for (int k = 0; k < DIM / 32; k++) {
            int d = lane + 32 * k;
            float nv = __ldg(nrow + d);
            nn += nv * nv;
#pragma unroll
            for (int i = 0; i < 8; i++) acc[i] += nv * s_a[i][d];
        }
        nn = warp_sum(nn);
#pragma unroll
        for (int i = 0; i < 8; i++) acc[i] = warp_sum(acc[i]);
        if (lane == 0) {
            float invn = rsqrtf(fmaxf(nn, 1e-24f));
#pragma unroll
            for (int i = 0; i < 8; i++) {
                float sim = acc[i] * invn * TEMP_INV;
                p[i] += __expf(sim);
                if (self && (a0 + i) == j) g_pos[gidx0 + i] = sim;
            }
        }
    }
    if (lane == 0) {
#pragma unroll
        for (int i = 0; i < 8; i++) s_part[warp][i] = p[i];
    }

    // positives (non-self, chunk 0): warp w -> anchor w, normalize on the fly
    if (!self && chunk == 0) {
        const float* prow = Pv + (size_t)(a0 + warp) * DIM;
        float d0 = 0.f, pp = 0.f;
#pragma unroll 4
        for (int k = 0; k < DIM / 32; k++) {
            int d = lane + 32 * k;
            float pv = __ldg(prow + d);
            pp += pv * pv;
            d0 += pv * s_a[warp][d];
        }
        d0 = warp_sum(d0);
        pp = warp_sum(pp);
        if (lane == 0)
            g_pos[gidx0 + warp] = d0 * rsqrtf(fmaxf(pp, 1e-24f)) * TEMP_INV;
    }
    __syncthreads();

    if (t < 8) {
        float s = 0.f;
#pragma unroll
        for (int w = 0; w < 8; w++) s += s_part[w][t];
        g_part[(gidx0 + t) * MAXCHUNK + chunk] = s;
    }
}

// ============================================================================
// K_FINAL: finish per-anchor losses + nll mean (gated by labels) -> d_out[0]
// ============================================================================
__global__ void __launch_bounds__(1024) k_final(
    const int* __restrict__ labels32, float* __restrict__ out)
{
    __shared__ int s_is64;
    int t = threadIdx.x, lane = t & 31, warp = t >> 5;
    if (t == 0) s_is64 = sniff_is64(labels32);
    __syncthreads();
    const int is64 = s_is64;

    float contrib = 0.f;
    if (t < 224) {                       // line
        float s = 0.f;
#pragma unroll
        for (int c = 0; c < 7; c++) s += g_part[t * MAXCHUNK + c];
        float pos = g_pos[t];
        contrib = (W_LINE / (float)P_LINE) * (__logf(s + __expf(pos)) - pos);
    } else if (t < 288) {                // quat
        float s = g_part[t * MAXCHUNK + 0] + g_part[t * MAXCHUNK + 1];
        float pos = g_pos[t];
        contrib = (W_QUAT / (float)P_QUAT) * (__logf(s + __expf(pos)) - pos);
    } else if (t < 304) {                // sonnet (diag already inside sum)
        float s = g_part[t * MAXCHUNK + 0];
        float pos = g_pos[t];
        contrib = (W_SONNET / (float)B_SON) * (__logf(s) - pos);
    }

    float nll = 0.f, cnt = 0.f;
    for (int i = t; i < NROWS; i += 1024) {
        int lab = is64 ? __ldg(labels32 + 2 * i) : __ldg(labels32 + i);
        if (lab >= 0) { nll += g_nll[i]; cnt += 1.f; }
    }

    __shared__ float r0[32], r1[32], r2[32];
    contrib = warp_sum(contrib);
    nll     = warp_sum(nll);
    cnt     = warp_sum(cnt);
    if (lane == 0) { r0[warp] = contrib; r1[warp] = nll; r2[warp] = cnt; }
    __syncthreads();
    if (t < 32) {
        float a = r0[t], bb = r1[t], c = r2[t];
        a = warp_sum(a);
        bb = warp_sum(bb);
        c = warp_sum(c);
        if (t == 0) {
            out[0] = a + W_MLM * (bb / fmaxf(c, 1.f));
        }
    }
}

// ============================================================================
extern "C" void kernel_launch(void* const* d_in, const int* in_sizes, int n_in,
                              void* d_out, int out_size)
{
    const float* logits = (const float*)d_in[0];
    const int*   labels = (const int*)  d_in[1];
    const float* la = (const float*)d_in[2];
    const float* lp = (const float*)d_in[3];
    const float* ln = (const float*)d_in[4];
    const float* qa = (const float*)d_in[5];
    const float* qp = (const float*)d_in[6];
    const float* qn = (const float*)d_in[7];
    const float* se = (const float*)d_in[8];

    k_main <<<GRID_MAIN, 256>>>(logits, labels, la, lp, ln, qa, qp, qn, se);
    k_final<<<1, 1024>>>(labels, (float*)d_out);
}